// round 15
// baseline (speedup 1.0000x reference)
#include <cuda_runtime.h>
#include <cuda_fp16.h>
#include <math.h>
#include <stdint.h>

#define NB 32
#define NS 256
#define NH 768
#define KC 16
#define NCHUNK (NH / KC)   // 48
#define ROWB 48            // 32B data + 16 pad; 12-bank stride -> conflict-free

// ---------------- device scratch ----------------
__device__ __half g_Qh[NB * NS * NH];
__device__ __half g_Kh[NB * NS * NH];
__device__ __half g_Kw[NB * NS * NH];     // decay-convolved K (scale included)
__device__ __half g_KsumH[NB * NH];       // masked K column sums (fp16)
__device__ float g_Mj[NB];                // valid-key counts
__device__ float g_w[NS];
__device__ float g_Sw[NB * NB * NS];      // q . Kw   per (i,j,s)
__device__ float g_Srow[NB * NB * NS];    // q . Ksum per (i,j,s)
__device__ float g_partial[NB * NB];

// ---------------- band smem layout (KC=16, 3 buffers, 1 j per CTA) ----------
#define O_A   0                       // 256*48 = 12288
#define O_B   12288
#define BUF_SZ 24576
#define O_WS  (3 * BUF_SZ)            // 73728
#define O_KM  (O_WS + 1024)
#define O_QM  (O_KM + 1024)
#define O_RED (O_QM + 1024)
#define SMEM_NEED (O_RED + 64)        // 76864; x2 CTA = 153728 <= 227KB

// ---------------- swrow smem layout ----------------
#define AST   1552
#define SW_A  0
#define SW_B  49664
#define SW_RED (96 * AST)             // 148992
#define SW_SMEM (SW_RED + 8 * 2048 * 4)   // 214528

// ---------------- conv smem ----------------
#define CONV_SMEM (131072 + 1024)     // fbuf[256][256] half + kms[256]

// ---------------- PTX helpers (base ISA only) ----------------
__device__ __forceinline__ uint32_t smem_u32(const void* p) {
    uint32_t a;
    asm("{ .reg .u64 t; cvta.to.shared.u64 t, %1; cvt.u32.u64 %0, t; }" : "=r"(a) : "l"(p));
    return a;
}
__device__ __forceinline__ void cpasync16(uint32_t s, const void* g) {
    asm volatile("cp.async.cg.shared.global [%0], [%1], 16;" :: "r"(s), "l"(g));
}
#define CP_COMMIT() asm volatile("cp.async.commit_group;" ::: "memory")
#define CP_WAIT0()  asm volatile("cp.async.wait_group 0;" ::: "memory")
#define CP_WAIT1()  asm volatile("cp.async.wait_group 1;" ::: "memory")

__device__ __forceinline__ void ldsm4(uint32_t (&r)[4], uint32_t a) {
    asm volatile("ldmatrix.sync.aligned.m8n8.x4.shared.b16 {%0,%1,%2,%3}, [%4];"
                 : "=r"(r[0]), "=r"(r[1]), "=r"(r[2]), "=r"(r[3]) : "r"(a));
}
__device__ __forceinline__ void hmma(float* d, const uint32_t (&a)[4],
                                     uint32_t b0, uint32_t b1) {
    asm volatile(
        "mma.sync.aligned.m16n8k16.row.col.f32.f16.f16.f32 "
        "{%0,%1,%2,%3}, {%4,%5,%6,%7}, {%8,%9}, {%0,%1,%2,%3};"
        : "+f"(d[0]), "+f"(d[1]), "+f"(d[2]), "+f"(d[3])
        : "r"(a[0]), "r"(a[1]), "r"(a[2]), "r"(a[3]), "r"(b0), "r"(b1));
}

// ---------------------------------------------------------------------------
// Prep: one WARP per row. Block 0 also builds g_w.
// ---------------------------------------------------------------------------
__global__ void __launch_bounds__(256)
norm_all_kernel(const float* __restrict__ q, const float* __restrict__ k,
                const float* __restrict__ alpha_raw,
                const float* __restrict__ logit_scale) {
    int tid = threadIdx.x, wid = tid >> 5, lid = tid & 31;

    if (blockIdx.x == 0) {
        float a = alpha_raw[0];
        float alpha = (a > 20.f) ? a : log1pf(expf(a));
        float scale = expf(logit_scale[0]);
        g_w[tid] = scale * expf(-alpha * (float)tid);
    }

    int row = blockIdx.x * 8 + wid;
    int which = row >= NB * NS;
    int r = which ? row - NB * NS : row;
    const float4* x = (const float4*)((which ? k : q) + (size_t)r * NH);

    float4 v[6];
    float ss = 0.f;
    #pragma unroll
    for (int t = 0; t < 6; ++t) {
        v[t] = x[lid + 32 * t];
        ss += v[t].x * v[t].x + v[t].y * v[t].y + v[t].z * v[t].z + v[t].w * v[t].w;
    }
    #pragma unroll
    for (int o = 16; o; o >>= 1) ss += __shfl_xor_sync(0xffffffffu, ss, o);
    float inv = 1.f / fmaxf(sqrtf(ss), 1e-12f);

    __half2* dst = (__half2*)((which ? g_Kh : g_Qh) + (size_t)r * NH);
    #pragma unroll
    for (int t = 0; t < 6; ++t) {
        int h2 = 2 * (lid + 32 * t);
        dst[h2]     = __floats2half2_rn(v[t].x * inv, v[t].y * inv);
        dst[h2 + 1] = __floats2half2_rn(v[t].z * inv, v[t].w * inv);
    }
}

// ---------------------------------------------------------------------------
// Conv v2 (proven R14): batched loads + smem forward-intermediate.
// ---------------------------------------------------------------------------
#define CONV_LOAD(ARR, T0)                                                    \
    _Pragma("unroll")                                                         \
    for (int u = 0; u < 16; ++u)                                              \
        ARR[u] = kms[(T0) + u] * __half2float(kp[(size_t)((T0) + u) * NH]);

#define CONV_LOADR(ARR, T0)                                                   \
    _Pragma("unroll")                                                         \
    for (int u = 0; u < 16; ++u)                                              \
        ARR[u] = kms[(T0) - u] * __half2float(kp[(size_t)((T0) - u) * NH]);

__global__ void __launch_bounds__(256, 1)
conv_kernel(const float* __restrict__ kmask,
            const float* __restrict__ alpha_raw,
            const float* __restrict__ logit_scale) {
    extern __shared__ char sm[];
    __half* fbuf = (__half*)sm;                // [256 t][256 h]
    float* kms = (float*)(sm + 131072);
    int j = blockIdx.x / 3;
    int hb = blockIdx.x % 3;
    int tid = threadIdx.x;
    int h = hb * 256 + tid;
    kms[tid] = (kmask[j * NS + tid] > 0.f) ? 1.f : 0.f;
    __syncthreads();

    float a = alpha_raw[0];
    float alpha = (a > 20.f) ? a : log1pf(expf(a));
    float r = expf(-alpha);
    float scale = expf(logit_scale[0]);

    const __half* kp = g_Kh + (size_t)j * NS * NH + h;
    __half* kwp = g_Kw + (size_t)j * NS * NH + h;

    float a0[16], a1[16];
    float f = 0.f, ksum = 0.f;

    CONV_LOAD(a0, 0);
    #pragma unroll
    for (int pp = 0; pp < 8; ++pp) {
        int p0 = 2 * pp;
        if (p0 + 1 < 16) { CONV_LOAD(a1, (p0 + 1) * 16); }
        #pragma unroll
        for (int u = 0; u < 16; ++u) {
            int t = p0 * 16 + u;
            ksum += a0[u];
            f = a0[u] + r * f;
            fbuf[t * 256 + tid] = __float2half(scale * f);
        }
        if (p0 + 2 < 16) { CONV_LOAD(a0, (p0 + 2) * 16); }
        #pragma unroll
        for (int u = 0; u < 16; ++u) {
            int t = (p0 + 1) * 16 + u;
            ksum += a1[u];
            f = a1[u] + r * f;
            fbuf[t * 256 + tid] = __float2half(scale * f);
        }
    }
    g_KsumH[j * NH + h] = __float2half(ksum);

    float g = 0.f;
    CONV_LOADR(a0, 255);
    #pragma unroll
    for (int pp = 0; pp < 8; ++pp) {
        int p0 = 2 * pp;
        if (p0 + 1 < 16) { CONV_LOADR(a1, 255 - (p0 + 1) * 16); }
        #pragma unroll
        for (int u = 0; u < 16; ++u) {
            int t = 255 - (p0 * 16 + u);
            float gA = r * g;
            float prev = __half2float(fbuf[t * 256 + tid]);
            kwp[(size_t)t * NH] = __float2half(prev + scale * gA);
            g = a0[u] + gA;
        }
        if (p0 + 2 < 16) { CONV_LOADR(a0, 255 - (p0 + 2) * 16); }
        #pragma unroll
        for (int u = 0; u < 16; ++u) {
            int t = 255 - ((p0 + 1) * 16 + u);
            float gA = r * g;
            float prev = __half2float(fbuf[t * 256 + tid]);
            kwp[(size_t)t * NH] = __float2half(prev + scale * gA);
            g = a1[u] + gA;
        }
    }

    if (hb == 0 && tid == 0) {
        float m = 0.f;
        for (int t = 0; t < NS; ++t) m += kms[t];
        g_Mj[j] = m;
    }
}

// ---------------------------------------------------------------------------
// Swrow (tensor-core, proven R13/14): one CTA per s, 32x64x768 GEMM.
// ---------------------------------------------------------------------------
__global__ void __launch_bounds__(256, 1)
swrow_kernel() {
    extern __shared__ char sm[];
    uint32_t sb = smem_u32(sm);
    int s = blockIdx.x;
    int tid = threadIdx.x, wid = tid >> 5, lid = tid & 31;

    #pragma unroll
    for (int it = 0; it < 12; ++it) {
        int idx = tid + it * 256;
        int r = idx / 96, g = idx - r * 96;
        cpasync16(sb + SW_A + (uint32_t)(r * AST + g * 16),
                  g_Qh + ((size_t)r * NS + s) * NH + g * 8);
    }
    #pragma unroll
    for (int it = 0; it < 24; ++it) {
        int idx = tid + it * 256;
        int r = idx / 96, g = idx - r * 96;
        const __half* src = (r < 32)
            ? g_Kw + ((size_t)r * NS + s) * NH + g * 8
            : g_KsumH + (size_t)(r - 32) * NH + g * 8;
        cpasync16(sb + SW_B + (uint32_t)(r * AST + g * 16), src);
    }
    CP_COMMIT();
    CP_WAIT0();
    __syncthreads();

    float acc[2][8][4];
    #pragma unroll
    for (int mf = 0; mf < 2; ++mf)
        #pragma unroll
        for (int nf = 0; nf < 8; ++nf)
            #pragma unroll
            for (int u = 0; u < 4; ++u) acc[mf][nf][u] = 0.f;

    uint32_t a_base = sb + SW_A + (lid & 15) * AST + ((lid >> 4) << 4);
    uint32_t b_base = sb + SW_B + (((lid >> 4) & 1) * 8 + (lid & 7)) * AST
                      + (((lid >> 3) & 1) << 4);

    #pragma unroll
    for (int step = 0; step < 6; ++step) {
        uint32_t kb = (uint32_t)(wid * 6 + step) * 32;
        uint32_t A0[4], A1[4];
        ldsm4(A0, a_base + kb);
        ldsm4(A1, a_base + 16 * AST + kb);
        #pragma unroll
        for (int nb = 0; nb < 4; ++nb) {
            uint32_t B[4];
            ldsm4(B, b_base + nb * 16 * AST + kb);
            hmma(acc[0][2 * nb],     A0, B[0], B[1]);
            hmma(acc[0][2 * nb + 1], A0, B[2], B[3]);
            hmma(acc[1][2 * nb],     A1, B[0], B[1]);
            hmma(acc[1][2 * nb + 1], A1, B[2], B[3]);
        }
    }
    __syncthreads();

    float* red = (float*)(sm + SW_RED);     // [8][2048]
    float* mine = red + wid * 2048;
    #pragma unroll
    for (int mf = 0; mf < 2; ++mf)
        #pragma unroll
        for (int nf = 0; nf < 8; ++nf)
            #pragma unroll
            for (int u = 0; u < 4; ++u) {
                int row = mf * 16 + (lid >> 2) + ((u >> 1) << 3);
                int col = nf * 8 + 2 * (lid & 3) + (u & 1);
                mine[row * 64 + col] = acc[mf][nf][u];
            }
    __syncthreads();

    #pragma unroll
    for (int it = 0; it < 8; ++it) {
        int idx = tid + it * 256;
        float v = 0.f;
        #pragma unroll
        for (int w = 0; w < 8; ++w) v += red[w * 2048 + idx];
        int row = idx >> 6, col = idx & 63;
        if (col < 32) g_Sw[((size_t)row * NB + col) * NS + s] = v;
        else          g_Srow[((size_t)row * NB + (col - 32)) * NS + s] = v;
    }
}

// ---------------------------------------------------------------------------
// Band v3: blk = j*32 + i (1 j per CTA, <=128 regs, 2 CTA/SM restored).
// KC=16, 3-buffer cp.async ring (prefetch distance 2), one barrier per chunk.
// 48-wide guarded windows per 16-row group (exact d<=16 coverage).
// ---------------------------------------------------------------------------
__device__ __forceinline__ void load_chunk(uint32_t sb, int buf, int c, int tid,
                                           const __half* Qp, const __half* Kp) {
    int k0 = c * KC;
    uint32_t bufb = sb + buf * BUF_SZ;
    #pragma unroll
    for (int it = 0; it < 2; ++it) {   // A: 256 rows x 2 groups = 512 (2/thread)
        int x = tid + it * 256;
        int r = x >> 1, g = x & 1;
        size_t go = (size_t)r * NH + k0 + g * 8;
        cpasync16(bufb + O_A + (uint32_t)(r * ROWB + g * 16), Qp + go);
    }
    #pragma unroll
    for (int it = 0; it < 2; ++it) {   // B: 256 rows x 2 groups = 512 (2/thread)
        int x = tid + it * 256;
        int r = x >> 1, g = x & 1;
        size_t go = (size_t)r * NH + k0 + g * 8;
        cpasync16(bufb + O_B + (uint32_t)(r * ROWB + g * 16), Kp + go);
    }
    CP_COMMIT();
}

__global__ void __launch_bounds__(256, 2)
li_band_kernel(const float* __restrict__ qmask, const float* __restrict__ kmask) {
    extern __shared__ char smem[];
    uint32_t sb = smem_u32(smem);

    int tid = threadIdx.x, wid = tid >> 5, lid = tid & 31;
    int blk = blockIdx.x;
    int j = blk >> 5;
    int i = blk & 31;

    float* ws = (float*)(smem + O_WS);
    float* km = (float*)(smem + O_KM);
    float* qm = (float*)(smem + O_QM);
    float* red = (float*)(smem + O_RED);
    ws[tid] = g_w[tid];
    km[tid] = kmask[j * NS + tid];
    qm[tid] = qmask[i * NS + tid];

    const __half* Qp = g_Qh + (size_t)i * NS * NH;
    const __half* Kp = g_Kh + (size_t)j * NS * NH;

    float acc[2][8][4];
    #pragma unroll
    for (int mf = 0; mf < 2; ++mf)
        #pragma unroll
        for (int nf = 0; nf < 8; ++nf)
            #pragma unroll
            for (int u = 0; u < 4; ++u) acc[mf][nf][u] = 0.f;

    int m_base = wid * 32;
    int wb = m_base - 16;
    if (wb < 0) wb = 0;
    if (wb > 192) wb = 192;
    int lo0 = (wid == 7) ? 1 : 0;
    int lo1 = (wid == 0) ? 0 : 1;

    uint32_t a_off = (uint32_t)((m_base + (lid & 15)) * ROWB + ((lid >> 4) << 4));
    uint32_t b_row = ((lid >> 4) & 1) * 8 + (lid & 7);
    uint32_t b_off = (uint32_t)((wb + b_row) * ROWB + ((lid >> 3) & 1) * 16);

    // prologue: chunks 0 and 1
    load_chunk(sb, 0, 0, tid, Qp, Kp);
    load_chunk(sb, 1, 1, tid, Qp, Kp);

    int buf = 0;
    for (int c = 0; c < NCHUNK; ++c) {
        if (c + 1 < NCHUNK) { CP_WAIT1(); } else { CP_WAIT0(); }
        __syncthreads();
        if (c + 2 < NCHUNK) {
            int nbuf = buf + 2; if (nbuf >= 3) nbuf -= 3;
            load_chunk(sb, nbuf, c + 2, tid, Qp, Kp);
        }

        uint32_t base = sb + buf * BUF_SZ;
        uint32_t A0[4], A1[4], Bf[2][4];
        ldsm4(A0, base + O_A + a_off);
        ldsm4(A1, base + O_A + a_off + 16 * ROWB);
        ldsm4(Bf[0], base + O_B + b_off);
        #pragma unroll
        for (int nb = 0; nb < 4; ++nb) {
            int cur = nb & 1;
            if (nb < 3)
                ldsm4(Bf[cur ^ 1], base + O_B + b_off + (nb + 1) * 16 * ROWB);
            if (nb >= lo0 && nb <= lo0 + 2) {
                hmma(acc[0][2 * nb],     A0, Bf[cur][0], Bf[cur][1]);
                hmma(acc[0][2 * nb + 1], A0, Bf[cur][2], Bf[cur][3]);
            }
            if (nb >= lo1 && nb <= lo1 + 2) {
                hmma(acc[1][2 * nb],     A1, Bf[cur][0], Bf[cur][1]);
                hmma(acc[1][2 * nb + 1], A1, Bf[cur][2], Bf[cur][3]);
            }
        }
        ++buf; if (buf >= 3) buf -= 3;
    }
    __syncthreads();

    // ---- epilogue: near-band exact + linear far field (unchanged) ----
    float shift = ws[0];
    float E = expf(-shift);
    float Mjv = g_Mj[j];
    const float* SwP = g_Sw + ((size_t)i * NB + j) * NS;
    const float* SrP = g_Srow + ((size_t)i * NB + j) * NS;

    int cb = 2 * (lid & 3);
    int rloc = lid >> 2;
    float warp_score = 0.f;
    #pragma unroll
    for (int mf = 0; mf < 2; ++mf) {
        int lo = mf ? lo1 : lo0;
        #pragma unroll
        for (int half = 0; half < 2; ++half) {
            int s = m_base + mf * 16 + rloc + half * 8;
            float cse = 0.f, csec = 0.f;
            #pragma unroll
            for (int nf = 0; nf < 8; ++nf) {
                if (nf >= 2 * lo && nf < 2 * lo + 6) {
                    #pragma unroll
                    for (int cc = 0; cc < 2; ++cc) {
                        int t = wb + nf * 8 + cb + cc;
                        if (km[t] > 0.f) {
                            float sim = acc[mf][nf][half * 2 + cc];
                            int d = s - t; d = d < 0 ? -d : d;
                            float l = sim * ws[d];
                            float e = __expf(l - shift);
                            cse += e - E * (1.f + l);
                            csec = fmaf(e - E, sim, csec);
                        }
                    }
                }
            }
            cse  += __shfl_xor_sync(0xffffffffu, cse, 1);
            cse  += __shfl_xor_sync(0xffffffffu, cse, 2);
            csec += __shfl_xor_sync(0xffffffffu, csec, 1);
            csec += __shfl_xor_sync(0xffffffffu, csec, 2);
            if ((lid & 3) == 0) {
                float qms = qm[s];
                float se = E * (Mjv + SwP[s]) + cse;
                float sec = E * SrP[s] + csec;
                if (se > 0.f && qms > 0.f) warp_score += (sec / se) * qms;
            }
        }
    }
    #pragma unroll
    for (int o = 16; o; o >>= 1)
        warp_score += __shfl_xor_sync(0xffffffffu, warp_score, o);
    if (lid == 0) red[wid] = warp_score;
    __syncthreads();
    if (tid == 0) {
        float tot = 0.f;
        #pragma unroll
        for (int w = 0; w < 8; ++w) tot += red[w];
        g_partial[blk] = tot;
    }
}

// ---------------------------------------------------------------------------
__global__ void reduce_kernel(const float* __restrict__ qmask, float* __restrict__ out) {
    int i = blockIdx.x;
    int tid = threadIdx.x;
    float v = qmask[i * NS + tid];
    #pragma unroll
    for (int o = 16; o; o >>= 1) v += __shfl_xor_sync(0xffffffffu, v, o);
    __shared__ float red[8];
    __shared__ float qsum_s;
    if ((tid & 31) == 0) red[tid >> 5] = v;
    __syncthreads();
    if (tid == 0) {
        float t = 0.f;
        #pragma unroll
        for (int w = 0; w < 8; ++w) t += red[w];
        qsum_s = fmaxf(t, 1.f);
    }
    __syncthreads();
    if (tid < NB) {
        int jj = tid;
        out[i * NB + jj] = g_partial[jj * NB + i] / qsum_s;
    }
}

extern "C" void kernel_launch(void* const* d_in, const int* in_sizes, int n_in,
                              void* d_out, int out_size) {
    const float* q           = (const float*)d_in[0];
    const float* k           = (const float*)d_in[1];
    const float* qmask       = (const float*)d_in[2];
    const float* kmask       = (const float*)d_in[3];
    const float* alpha_raw   = (const float*)d_in[4];
    const float* logit_scale = (const float*)d_in[5];
    float* out = (float*)d_out;

    cudaFuncSetAttribute(li_band_kernel, cudaFuncAttributeMaxDynamicSharedMemorySize, SMEM_NEED);
    cudaFuncSetAttribute(swrow_kernel, cudaFuncAttributeMaxDynamicSharedMemorySize, SW_SMEM);
    cudaFuncSetAttribute(conv_kernel, cudaFuncAttributeMaxDynamicSharedMemorySize, CONV_SMEM);

    norm_all_kernel<<<2 * NB * NS / 8, 256>>>(q, k, alpha_raw, logit_scale);
    conv_kernel<<<NB * 3, 256, CONV_SMEM>>>(kmask, alpha_raw, logit_scale);
    swrow_kernel<<<NS, 256, SW_SMEM>>>();
    li_band_kernel<<<NB * NB, 256, SMEM_NEED>>>(qmask, kmask);
    reduce_kernel<<<NB, 256>>>(qmask, out);
}

// round 16
// speedup vs baseline: 1.2177x; 1.2177x over previous
#include <cuda_runtime.h>
#include <cuda_fp16.h>
#include <math.h>
#include <stdint.h>

#define NB 32
#define NS 256
#define NH 768
#define KC 32
#define NCHUNK (NH / KC)   // 24
#define ROWB 80            // 64B data + 16 pad, conflict-free

// ---------------- device scratch ----------------
__device__ __half g_Qh[NB * NS * NH];
__device__ __half g_Kh[NB * NS * NH];
__device__ __half g_Kw[NB * NS * NH];     // decay-convolved K (scale included)
__device__ __half g_KsumH[NB * NH];       // masked K column sums (fp16)
__device__ float g_Mj[NB];                // valid-key counts
__device__ float g_w[NS];
__device__ float g_Sw[NB * NB * NS];      // q . Kw   per (i,j,s)
__device__ float g_Srow[NB * NB * NS];    // q . Ksum per (i,j,s)
__device__ float g_partial[NB * NB];

// ---------------- band smem layout (R13 shape: KC=32, 2 buffers) ----------
#define O_A   0                       // 256*80 = 20480
#define O_B   20480
#define BUF_SZ 40960
#define O_WS  (2 * BUF_SZ)            // 81920
#define O_KM  (O_WS + 1024)
#define O_QM  (O_KM + 1024)
#define O_RED (O_QM + 1024)
#define SMEM_NEED (O_RED + 64)        // 84544; x2 CTA <= 227KB

// ---------------- swrow smem layout ----------------
#define AST   1552
#define SW_A  0
#define SW_B  49664
#define SW_RED (96 * AST)             // 148992
#define SW_SMEM (SW_RED + 8 * 2048 * 4)   // 214528

// ---------------- conv smem ----------------
#define CONV_SMEM (131072 + 1024)     // fbuf[256][256] half + kms[256]

// ---------------- PTX helpers (base ISA only) ----------------
__device__ __forceinline__ uint32_t smem_u32(const void* p) {
    uint32_t a;
    asm("{ .reg .u64 t; cvta.to.shared.u64 t, %1; cvt.u32.u64 %0, t; }" : "=r"(a) : "l"(p));
    return a;
}
__device__ __forceinline__ void cpasync16(uint32_t s, const void* g) {
    asm volatile("cp.async.cg.shared.global [%0], [%1], 16;" :: "r"(s), "l"(g));
}
#define CP_COMMIT() asm volatile("cp.async.commit_group;" ::: "memory")
#define CP_WAIT0()  asm volatile("cp.async.wait_group 0;" ::: "memory")

__device__ __forceinline__ void ldsm4(uint32_t (&r)[4], uint32_t a) {
    asm volatile("ldmatrix.sync.aligned.m8n8.x4.shared.b16 {%0,%1,%2,%3}, [%4];"
                 : "=r"(r[0]), "=r"(r[1]), "=r"(r[2]), "=r"(r[3]) : "r"(a));
}
__device__ __forceinline__ void hmma(float* d, const uint32_t (&a)[4],
                                     uint32_t b0, uint32_t b1) {
    asm volatile(
        "mma.sync.aligned.m16n8k16.row.col.f32.f16.f16.f32 "
        "{%0,%1,%2,%3}, {%4,%5,%6,%7}, {%8,%9}, {%0,%1,%2,%3};"
        : "+f"(d[0]), "+f"(d[1]), "+f"(d[2]), "+f"(d[3])
        : "r"(a[0]), "r"(a[1]), "r"(a[2]), "r"(a[3]), "r"(b0), "r"(b1));
}

// ---------------------------------------------------------------------------
// Prep: one WARP per row. Block 0 also builds g_w.
// ---------------------------------------------------------------------------
__global__ void __launch_bounds__(256)
norm_all_kernel(const float* __restrict__ q, const float* __restrict__ k,
                const float* __restrict__ alpha_raw,
                const float* __restrict__ logit_scale) {
    int tid = threadIdx.x, wid = tid >> 5, lid = tid & 31;

    if (blockIdx.x == 0) {
        float a = alpha_raw[0];
        float alpha = (a > 20.f) ? a : log1pf(expf(a));
        float scale = expf(logit_scale[0]);
        g_w[tid] = scale * expf(-alpha * (float)tid);
    }

    int row = blockIdx.x * 8 + wid;
    int which = row >= NB * NS;
    int r = which ? row - NB * NS : row;
    const float4* x = (const float4*)((which ? k : q) + (size_t)r * NH);

    float4 v[6];
    float ss = 0.f;
    #pragma unroll
    for (int t = 0; t < 6; ++t) {
        v[t] = x[lid + 32 * t];
        ss += v[t].x * v[t].x + v[t].y * v[t].y + v[t].z * v[t].z + v[t].w * v[t].w;
    }
    #pragma unroll
    for (int o = 16; o; o >>= 1) ss += __shfl_xor_sync(0xffffffffu, ss, o);
    float inv = 1.f / fmaxf(sqrtf(ss), 1e-12f);

    __half2* dst = (__half2*)((which ? g_Kh : g_Qh) + (size_t)r * NH);
    #pragma unroll
    for (int t = 0; t < 6; ++t) {
        int h2 = 2 * (lid + 32 * t);
        dst[h2]     = __floats2half2_rn(v[t].x * inv, v[t].y * inv);
        dst[h2 + 1] = __floats2half2_rn(v[t].z * inv, v[t].w * inv);
    }
}

// ---------------------------------------------------------------------------
// Conv v2 (proven R14): batched loads + smem forward-intermediate.
// ---------------------------------------------------------------------------
#define CONV_LOAD(ARR, T0)                                                    \
    _Pragma("unroll")                                                         \
    for (int u = 0; u < 16; ++u)                                              \
        ARR[u] = kms[(T0) + u] * __half2float(kp[(size_t)((T0) + u) * NH]);

#define CONV_LOADR(ARR, T0)                                                   \
    _Pragma("unroll")                                                         \
    for (int u = 0; u < 16; ++u)                                              \
        ARR[u] = kms[(T0) - u] * __half2float(kp[(size_t)((T0) - u) * NH]);

__global__ void __launch_bounds__(256, 1)
conv_kernel(const float* __restrict__ kmask,
            const float* __restrict__ alpha_raw,
            const float* __restrict__ logit_scale) {
    extern __shared__ char sm[];
    __half* fbuf = (__half*)sm;                // [256 t][256 h]
    float* kms = (float*)(sm + 131072);
    int j = blockIdx.x / 3;
    int hb = blockIdx.x % 3;
    int tid = threadIdx.x;
    int h = hb * 256 + tid;
    kms[tid] = (kmask[j * NS + tid] > 0.f) ? 1.f : 0.f;
    __syncthreads();

    float a = alpha_raw[0];
    float alpha = (a > 20.f) ? a : log1pf(expf(a));
    float r = expf(-alpha);
    float scale = expf(logit_scale[0]);

    const __half* kp = g_Kh + (size_t)j * NS * NH + h;
    __half* kwp = g_Kw + (size_t)j * NS * NH + h;

    float a0[16], a1[16];
    float f = 0.f, ksum = 0.f;

    CONV_LOAD(a0, 0);
    #pragma unroll
    for (int pp = 0; pp < 8; ++pp) {
        int p0 = 2 * pp;
        if (p0 + 1 < 16) { CONV_LOAD(a1, (p0 + 1) * 16); }
        #pragma unroll
        for (int u = 0; u < 16; ++u) {
            int t = p0 * 16 + u;
            ksum += a0[u];
            f = a0[u] + r * f;
            fbuf[t * 256 + tid] = __float2half(scale * f);
        }
        if (p0 + 2 < 16) { CONV_LOAD(a0, (p0 + 2) * 16); }
        #pragma unroll
        for (int u = 0; u < 16; ++u) {
            int t = (p0 + 1) * 16 + u;
            ksum += a1[u];
            f = a1[u] + r * f;
            fbuf[t * 256 + tid] = __float2half(scale * f);
        }
    }
    g_KsumH[j * NH + h] = __float2half(ksum);

    float g = 0.f;
    CONV_LOADR(a0, 255);
    #pragma unroll
    for (int pp = 0; pp < 8; ++pp) {
        int p0 = 2 * pp;
        if (p0 + 1 < 16) { CONV_LOADR(a1, 255 - (p0 + 1) * 16); }
        #pragma unroll
        for (int u = 0; u < 16; ++u) {
            int t = 255 - (p0 * 16 + u);
            float gA = r * g;
            float prev = __half2float(fbuf[t * 256 + tid]);
            kwp[(size_t)t * NH] = __float2half(prev + scale * gA);
            g = a0[u] + gA;
        }
        if (p0 + 2 < 16) { CONV_LOADR(a0, 255 - (p0 + 2) * 16); }
        #pragma unroll
        for (int u = 0; u < 16; ++u) {
            int t = 255 - ((p0 + 1) * 16 + u);
            float gA = r * g;
            float prev = __half2float(fbuf[t * 256 + tid]);
            kwp[(size_t)t * NH] = __float2half(prev + scale * gA);
            g = a1[u] + gA;
        }
    }

    if (hb == 0 && tid == 0) {
        float m = 0.f;
        for (int t = 0; t < NS; ++t) m += kms[t];
        g_Mj[j] = m;
    }
}

// ---------------------------------------------------------------------------
// Swrow (tensor-core, proven R13/14): one CTA per s, 32x64x768 GEMM.
// ---------------------------------------------------------------------------
__global__ void __launch_bounds__(256, 1)
swrow_kernel() {
    extern __shared__ char sm[];
    uint32_t sb = smem_u32(sm);
    int s = blockIdx.x;
    int tid = threadIdx.x, wid = tid >> 5, lid = tid & 31;

    #pragma unroll
    for (int it = 0; it < 12; ++it) {
        int idx = tid + it * 256;
        int r = idx / 96, g = idx - r * 96;
        cpasync16(sb + SW_A + (uint32_t)(r * AST + g * 16),
                  g_Qh + ((size_t)r * NS + s) * NH + g * 8);
    }
    #pragma unroll
    for (int it = 0; it < 24; ++it) {
        int idx = tid + it * 256;
        int r = idx / 96, g = idx - r * 96;
        const __half* src = (r < 32)
            ? g_Kw + ((size_t)r * NS + s) * NH + g * 8
            : g_KsumH + (size_t)(r - 32) * NH + g * 8;
        cpasync16(sb + SW_B + (uint32_t)(r * AST + g * 16), src);
    }
    CP_COMMIT();
    CP_WAIT0();
    __syncthreads();

    float acc[2][8][4];
    #pragma unroll
    for (int mf = 0; mf < 2; ++mf)
        #pragma unroll
        for (int nf = 0; nf < 8; ++nf)
            #pragma unroll
            for (int u = 0; u < 4; ++u) acc[mf][nf][u] = 0.f;

    uint32_t a_base = sb + SW_A + (lid & 15) * AST + ((lid >> 4) << 4);
    uint32_t b_base = sb + SW_B + (((lid >> 4) & 1) * 8 + (lid & 7)) * AST
                      + (((lid >> 3) & 1) << 4);

    #pragma unroll
    for (int step = 0; step < 6; ++step) {
        uint32_t kb = (uint32_t)(wid * 6 + step) * 32;
        uint32_t A0[4], A1[4];
        ldsm4(A0, a_base + kb);
        ldsm4(A1, a_base + 16 * AST + kb);
        #pragma unroll
        for (int nb = 0; nb < 4; ++nb) {
            uint32_t B[4];
            ldsm4(B, b_base + nb * 16 * AST + kb);
            hmma(acc[0][2 * nb],     A0, B[0], B[1]);
            hmma(acc[0][2 * nb + 1], A0, B[2], B[3]);
            hmma(acc[1][2 * nb],     A1, B[0], B[1]);
            hmma(acc[1][2 * nb + 1], A1, B[2], B[3]);
        }
    }
    __syncthreads();

    float* red = (float*)(sm + SW_RED);     // [8][2048]
    float* mine = red + wid * 2048;
    #pragma unroll
    for (int mf = 0; mf < 2; ++mf)
        #pragma unroll
        for (int nf = 0; nf < 8; ++nf)
            #pragma unroll
            for (int u = 0; u < 4; ++u) {
                int row = mf * 16 + (lid >> 2) + ((u >> 1) << 3);
                int col = nf * 8 + 2 * (lid & 3) + (u & 1);
                mine[row * 64 + col] = acc[mf][nf][u];
            }
    __syncthreads();

    #pragma unroll
    for (int it = 0; it < 8; ++it) {
        int idx = tid + it * 256;
        float v = 0.f;
        #pragma unroll
        for (int w = 0; w < 8; ++w) v += red[w * 2048 + idx];
        int row = idx >> 6, col = idx & 63;
        if (col < 32) g_Sw[((size_t)row * NB + col) * NS + s] = v;
        else          g_Srow[((size_t)row * NB + (col - 32)) * NS + s] = v;
    }
}

// ---------------------------------------------------------------------------
// Band kernel (proven R13 shape): blk = j*32 + i, KC=32, 2 buffers,
// one barrier per chunk, 48-wide guarded windows per 16-row group.
// ---------------------------------------------------------------------------
__device__ __forceinline__ void load_chunk(uint32_t sb, int buf, int c, int tid,
                                           const __half* Qp, const __half* Kp) {
    int k0 = c * KC;
    uint32_t bufb = sb + buf * BUF_SZ;
    #pragma unroll
    for (int it = 0; it < 4; ++it) {
        int x = tid + it * 256;
        int r = x >> 2, g = x & 3;
        size_t go = (size_t)r * NH + k0 + g * 8;
        cpasync16(bufb + O_A + (uint32_t)(r * ROWB + g * 16), Qp + go);
    }
    #pragma unroll
    for (int it = 0; it < 4; ++it) {
        int x = tid + it * 256;
        int r = x >> 2, g = x & 3;
        size_t go = (size_t)r * NH + k0 + g * 8;
        cpasync16(bufb + O_B + (uint32_t)(r * ROWB + g * 16), Kp + go);
    }
    CP_COMMIT();
}

__global__ void __launch_bounds__(256, 2)
li_band_kernel(const float* __restrict__ qmask, const float* __restrict__ kmask) {
    extern __shared__ char smem[];
    uint32_t sb = smem_u32(smem);

    int tid = threadIdx.x, wid = tid >> 5, lid = tid & 31;
    int blk = blockIdx.x;
    int j = blk >> 5;
    int i = blk & 31;

    float* ws = (float*)(smem + O_WS);
    float* km = (float*)(smem + O_KM);
    float* qm = (float*)(smem + O_QM);
    float* red = (float*)(smem + O_RED);
    ws[tid] = g_w[tid];
    km[tid] = kmask[j * NS + tid];
    qm[tid] = qmask[i * NS + tid];

    const __half* Qp = g_Qh + (size_t)i * NS * NH;
    const __half* Kp = g_Kh + (size_t)j * NS * NH;

    float acc[2][8][4];
    #pragma unroll
    for (int mf = 0; mf < 2; ++mf)
        #pragma unroll
        for (int nf = 0; nf < 8; ++nf)
            #pragma unroll
            for (int u = 0; u < 4; ++u) acc[mf][nf][u] = 0.f;

    int m_base = wid * 32;
    int wb = m_base - 16;
    if (wb < 0) wb = 0;
    if (wb > 192) wb = 192;
    int lo0 = (wid == 7) ? 1 : 0;
    int lo1 = (wid == 0) ? 0 : 1;

    uint32_t a_off = (uint32_t)((m_base + (lid & 15)) * ROWB + ((lid >> 4) << 4));
    uint32_t b_row = ((lid >> 4) & 1) * 8 + (lid & 7);
    uint32_t b_off = (uint32_t)((wb + b_row) * ROWB + ((lid >> 3) & 1) * 16);

    load_chunk(sb, 0, 0, tid, Qp, Kp);

    for (int c = 0; c < NCHUNK; ++c) {
        CP_WAIT0();
        __syncthreads();
        if (c + 1 < NCHUNK)
            load_chunk(sb, (c + 1) & 1, c + 1, tid, Qp, Kp);

        uint32_t base = sb + (c & 1) * BUF_SZ;
        uint32_t A0[2][4], A1[2][4], Bf[2][4];
        ldsm4(A0[0], base + O_A + a_off);
        ldsm4(A1[0], base + O_A + a_off + 16 * ROWB);
        ldsm4(Bf[0], base + O_B + b_off);
        ldsm4(A0[1], base + O_A + a_off + 32);
        ldsm4(A1[1], base + O_A + a_off + 16 * ROWB + 32);
        #pragma unroll
        for (int t = 0; t < 8; ++t) {
            int ks = t >> 2, nb = t & 3;
            int cur = t & 1;
            if (t < 7) {
                int t1 = t + 1, ks1 = t1 >> 2, nb1 = t1 & 3;
                ldsm4(Bf[cur ^ 1], base + O_B + b_off + nb1 * 16 * ROWB + ks1 * 32);
            }
            if (nb >= lo0 && nb <= lo0 + 2) {
                hmma(acc[0][2 * nb],     A0[ks], Bf[cur][0], Bf[cur][1]);
                hmma(acc[0][2 * nb + 1], A0[ks], Bf[cur][2], Bf[cur][3]);
            }
            if (nb >= lo1 && nb <= lo1 + 2) {
                hmma(acc[1][2 * nb],     A1[ks], Bf[cur][0], Bf[cur][1]);
                hmma(acc[1][2 * nb + 1], A1[ks], Bf[cur][2], Bf[cur][3]);
            }
        }
    }
    __syncthreads();

    float shift = ws[0];
    float E = expf(-shift);
    float Mjv = g_Mj[j];
    const float* SwP = g_Sw + ((size_t)i * NB + j) * NS;
    const float* SrP = g_Srow + ((size_t)i * NB + j) * NS;

    int cb = 2 * (lid & 3);
    int rloc = lid >> 2;
    float warp_score = 0.f;
    #pragma unroll
    for (int mf = 0; mf < 2; ++mf) {
        int lo = mf ? lo1 : lo0;
        #pragma unroll
        for (int half = 0; half < 2; ++half) {
            int s = m_base + mf * 16 + rloc + half * 8;
            float cse = 0.f, csec = 0.f;
            #pragma unroll
            for (int nf = 0; nf < 8; ++nf) {
                if (nf >= 2 * lo && nf < 2 * lo + 6) {
                    #pragma unroll
                    for (int cc = 0; cc < 2; ++cc) {
                        int t = wb + nf * 8 + cb + cc;
                        if (km[t] > 0.f) {
                            float sim = acc[mf][nf][half * 2 + cc];
                            int d = s - t; d = d < 0 ? -d : d;
                            float l = sim * ws[d];
                            float e = __expf(l - shift);
                            cse += e - E * (1.f + l);
                            csec = fmaf(e - E, sim, csec);
                        }
                    }
                }
            }
            cse  += __shfl_xor_sync(0xffffffffu, cse, 1);
            cse  += __shfl_xor_sync(0xffffffffu, cse, 2);
            csec += __shfl_xor_sync(0xffffffffu, csec, 1);
            csec += __shfl_xor_sync(0xffffffffu, csec, 2);
            if ((lid & 3) == 0) {
                float qms = qm[s];
                float se = E * (Mjv + SwP[s]) + cse;
                float sec = E * SrP[s] + csec;
                if (se > 0.f && qms > 0.f) warp_score += (sec / se) * qms;
            }
        }
    }
    #pragma unroll
    for (int o = 16; o; o >>= 1)
        warp_score += __shfl_xor_sync(0xffffffffu, warp_score, o);
    if (lid == 0) red[wid] = warp_score;
    __syncthreads();
    if (tid == 0) {
        float tot = 0.f;
        #pragma unroll
        for (int w = 0; w < 8; ++w) tot += red[w];
        g_partial[blk] = tot;
    }
}

// ---------------------------------------------------------------------------
__global__ void reduce_kernel(const float* __restrict__ qmask, float* __restrict__ out) {
    int i = blockIdx.x;
    int tid = threadIdx.x;
    float v = qmask[i * NS + tid];
    #pragma unroll
    for (int o = 16; o; o >>= 1) v += __shfl_xor_sync(0xffffffffu, v, o);
    __shared__ float red[8];
    __shared__ float qsum_s;
    if ((tid & 31) == 0) red[tid >> 5] = v;
    __syncthreads();
    if (tid == 0) {
        float t = 0.f;
        #pragma unroll
        for (int w = 0; w < 8; ++w) t += red[w];
        qsum_s = fmaxf(t, 1.f);
    }
    __syncthreads();
    if (tid < NB) {
        int jj = tid;
        out[i * NB + jj] = g_partial[jj * NB + i] / qsum_s;
    }
}

extern "C" void kernel_launch(void* const* d_in, const int* in_sizes, int n_in,
                              void* d_out, int out_size) {
    const float* q           = (const float*)d_in[0];
    const float* k           = (const float*)d_in[1];
    const float* qmask       = (const float*)d_in[2];
    const float* kmask       = (const float*)d_in[3];
    const float* alpha_raw   = (const float*)d_in[4];
    const float* logit_scale = (const float*)d_in[5];
    float* out = (float*)d_out;

    cudaFuncSetAttribute(li_band_kernel, cudaFuncAttributeMaxDynamicSharedMemorySize, SMEM_NEED);
    cudaFuncSetAttribute(swrow_kernel, cudaFuncAttributeMaxDynamicSharedMemorySize, SW_SMEM);
    cudaFuncSetAttribute(conv_kernel, cudaFuncAttributeMaxDynamicSharedMemorySize, CONV_SMEM);

    norm_all_kernel<<<2 * NB * NS / 8, 256>>>(q, k, alpha_raw, logit_scale);
    conv_kernel<<<NB * 3, 256, CONV_SMEM>>>(kmask, alpha_raw, logit_scale);
    swrow_kernel<<<NS, 256, SW_SMEM>>>();
    li_band_kernel<<<NB * NB, 256, SMEM_NEED>>>(qmask, kmask);
    reduce_kernel<<<NB, 256>>>(qmask, out);
}

// round 17
// speedup vs baseline: 1.3261x; 1.0890x over previous
#include <cuda_runtime.h>
#include <cuda_fp16.h>
#include <math.h>
#include <stdint.h>

#define NB 32
#define NS 256
#define NH 768
#define KC 32
#define NCHUNK (NH / KC)   // 24
#define ROWB 80            // 64B data + 16 pad, conflict-free

// ---------------- device scratch ----------------
__device__ __half g_Qh[NB * NS * NH];
__device__ __half g_Kh[NB * NS * NH];
__device__ __half g_Kw[NB * NS * NH];     // decay-convolved K (scale included)
__device__ __half g_KsumH[NB * NH];       // masked K column sums (fp16)
__device__ float g_Mj[NB];                // valid-key counts
__device__ float g_w[NS];
__device__ float g_Sw[NB * NB * NS];      // q . Kw   per (i,j,s)
__device__ float g_Srow[NB * NB * NS];    // q . Ksum per (i,j,s)
__device__ float g_partial[NB * NB];

// ---------------- band smem layout (KC=32, 2 buffers) ----------
#define O_A   0                       // 256*80 = 20480
#define O_B   20480
#define BUF_SZ 40960
#define O_WS  (2 * BUF_SZ)            // 81920
#define O_KM  (O_WS + 1024)
#define O_QM  (O_KM + 1024)
#define O_RED (O_QM + 1024)
#define SMEM_NEED (O_RED + 128)       // ~84.6KB; x2 CTA <= 227KB

// ---------------- swrow smem layout ----------------
#define AST   1552
#define SW_A  0
#define SW_B  49664
#define SW_RED (96 * AST)             // 148992
#define SW_SMEM (SW_RED + 8 * 2048 * 4)   // 214528

// ---------------- conv smem ----------------
#define CONV_SMEM (131072 + 1024)     // fbuf[256][256] half + kms[256]

// ---------------- PTX helpers (base ISA only) ----------------
__device__ __forceinline__ uint32_t smem_u32(const void* p) {
    uint32_t a;
    asm("{ .reg .u64 t; cvta.to.shared.u64 t, %1; cvt.u32.u64 %0, t; }" : "=r"(a) : "l"(p));
    return a;
}
__device__ __forceinline__ void cpasync16(uint32_t s, const void* g) {
    asm volatile("cp.async.cg.shared.global [%0], [%1], 16;" :: "r"(s), "l"(g));
}
#define CP_COMMIT() asm volatile("cp.async.commit_group;" ::: "memory")
#define CP_WAIT0()  asm volatile("cp.async.wait_group 0;" ::: "memory")

__device__ __forceinline__ void ldsm4(uint32_t (&r)[4], uint32_t a) {
    asm volatile("ldmatrix.sync.aligned.m8n8.x4.shared.b16 {%0,%1,%2,%3}, [%4];"
                 : "=r"(r[0]), "=r"(r[1]), "=r"(r[2]), "=r"(r[3]) : "r"(a));
}
__device__ __forceinline__ void hmma(float* d, const uint32_t (&a)[4],
                                     uint32_t b0, uint32_t b1) {
    asm volatile(
        "mma.sync.aligned.m16n8k16.row.col.f32.f16.f16.f32 "
        "{%0,%1,%2,%3}, {%4,%5,%6,%7}, {%8,%9}, {%0,%1,%2,%3};"
        : "+f"(d[0]), "+f"(d[1]), "+f"(d[2]), "+f"(d[3])
        : "r"(a[0]), "r"(a[1]), "r"(a[2]), "r"(a[3]), "r"(b0), "r"(b1));
}

// ---------------------------------------------------------------------------
// Prep: one WARP per row. Block 0 also builds g_w.
// ---------------------------------------------------------------------------
__global__ void __launch_bounds__(256)
norm_all_kernel(const float* __restrict__ q, const float* __restrict__ k,
                const float* __restrict__ alpha_raw,
                const float* __restrict__ logit_scale) {
    int tid = threadIdx.x, wid = tid >> 5, lid = tid & 31;

    if (blockIdx.x == 0) {
        float a = alpha_raw[0];
        float alpha = (a > 20.f) ? a : log1pf(expf(a));
        float scale = expf(logit_scale[0]);
        g_w[tid] = scale * expf(-alpha * (float)tid);
    }

    int row = blockIdx.x * 8 + wid;
    int which = row >= NB * NS;
    int r = which ? row - NB * NS : row;
    const float4* x = (const float4*)((which ? k : q) + (size_t)r * NH);

    float4 v[6];
    float ss = 0.f;
    #pragma unroll
    for (int t = 0; t < 6; ++t) {
        v[t] = x[lid + 32 * t];
        ss += v[t].x * v[t].x + v[t].y * v[t].y + v[t].z * v[t].z + v[t].w * v[t].w;
    }
    #pragma unroll
    for (int o = 16; o; o >>= 1) ss += __shfl_xor_sync(0xffffffffu, ss, o);
    float inv = 1.f / fmaxf(sqrtf(ss), 1e-12f);

    __half2* dst = (__half2*)((which ? g_Kh : g_Qh) + (size_t)r * NH);
    #pragma unroll
    for (int t = 0; t < 6; ++t) {
        int h2 = 2 * (lid + 32 * t);
        dst[h2]     = __floats2half2_rn(v[t].x * inv, v[t].y * inv);
        dst[h2 + 1] = __floats2half2_rn(v[t].z * inv, v[t].w * inv);
    }
}

// ---------------------------------------------------------------------------
// Conv v2 (proven R14): batched loads + smem forward-intermediate.
// ---------------------------------------------------------------------------
#define CONV_LOAD(ARR, T0)                                                    \
    _Pragma("unroll")                                                         \
    for (int u = 0; u < 16; ++u)                                              \
        ARR[u] = kms[(T0) + u] * __half2float(kp[(size_t)((T0) + u) * NH]);

#define CONV_LOADR(ARR, T0)                                                   \
    _Pragma("unroll")                                                         \
    for (int u = 0; u < 16; ++u)                                              \
        ARR[u] = kms[(T0) - u] * __half2float(kp[(size_t)((T0) - u) * NH]);

__global__ void __launch_bounds__(256, 1)
conv_kernel(const float* __restrict__ kmask,
            const float* __restrict__ alpha_raw,
            const float* __restrict__ logit_scale) {
    extern __shared__ char sm[];
    __half* fbuf = (__half*)sm;                // [256 t][256 h]
    float* kms = (float*)(sm + 131072);
    int j = blockIdx.x / 3;
    int hb = blockIdx.x % 3;
    int tid = threadIdx.x;
    int h = hb * 256 + tid;
    kms[tid] = (kmask[j * NS + tid] > 0.f) ? 1.f : 0.f;
    __syncthreads();

    float a = alpha_raw[0];
    float alpha = (a > 20.f) ? a : log1pf(expf(a));
    float r = expf(-alpha);
    float scale = expf(logit_scale[0]);

    const __half* kp = g_Kh + (size_t)j * NS * NH + h;
    __half* kwp = g_Kw + (size_t)j * NS * NH + h;

    float a0[16], a1[16];
    float f = 0.f, ksum = 0.f;

    CONV_LOAD(a0, 0);
    #pragma unroll
    for (int pp = 0; pp < 8; ++pp) {
        int p0 = 2 * pp;
        if (p0 + 1 < 16) { CONV_LOAD(a1, (p0 + 1) * 16); }
        #pragma unroll
        for (int u = 0; u < 16; ++u) {
            int t = p0 * 16 + u;
            ksum += a0[u];
            f = a0[u] + r * f;
            fbuf[t * 256 + tid] = __float2half(scale * f);
        }
        if (p0 + 2 < 16) { CONV_LOAD(a0, (p0 + 2) * 16); }
        #pragma unroll
        for (int u = 0; u < 16; ++u) {
            int t = (p0 + 1) * 16 + u;
            ksum += a1[u];
            f = a1[u] + r * f;
            fbuf[t * 256 + tid] = __float2half(scale * f);
        }
    }
    g_KsumH[j * NH + h] = __float2half(ksum);

    float g = 0.f;
    CONV_LOADR(a0, 255);
    #pragma unroll
    for (int pp = 0; pp < 8; ++pp) {
        int p0 = 2 * pp;
        if (p0 + 1 < 16) { CONV_LOADR(a1, 255 - (p0 + 1) * 16); }
        #pragma unroll
        for (int u = 0; u < 16; ++u) {
            int t = 255 - (p0 * 16 + u);
            float gA = r * g;
            float prev = __half2float(fbuf[t * 256 + tid]);
            kwp[(size_t)t * NH] = __float2half(prev + scale * gA);
            g = a0[u] + gA;
        }
        if (p0 + 2 < 16) { CONV_LOADR(a0, 255 - (p0 + 2) * 16); }
        #pragma unroll
        for (int u = 0; u < 16; ++u) {
            int t = 255 - ((p0 + 1) * 16 + u);
            float gA = r * g;
            float prev = __half2float(fbuf[t * 256 + tid]);
            kwp[(size_t)t * NH] = __float2half(prev + scale * gA);
            g = a1[u] + gA;
        }
    }

    if (hb == 0 && tid == 0) {
        float m = 0.f;
        for (int t = 0; t < NS; ++t) m += kms[t];
        g_Mj[j] = m;
    }
}

// ---------------------------------------------------------------------------
// Swrow (tensor-core, proven R13/14): one CTA per s, 32x64x768 GEMM.
// ---------------------------------------------------------------------------
__global__ void __launch_bounds__(256, 1)
swrow_kernel() {
    extern __shared__ char sm[];
    uint32_t sb = smem_u32(sm);
    int s = blockIdx.x;
    int tid = threadIdx.x, wid = tid >> 5, lid = tid & 31;

    #pragma unroll
    for (int it = 0; it < 12; ++it) {
        int idx = tid + it * 256;
        int r = idx / 96, g = idx - r * 96;
        cpasync16(sb + SW_A + (uint32_t)(r * AST + g * 16),
                  g_Qh + ((size_t)r * NS + s) * NH + g * 8);
    }
    #pragma unroll
    for (int it = 0; it < 24; ++it) {
        int idx = tid + it * 256;
        int r = idx / 96, g = idx - r * 96;
        const __half* src = (r < 32)
            ? g_Kw + ((size_t)r * NS + s) * NH + g * 8
            : g_KsumH + (size_t)(r - 32) * NH + g * 8;
        cpasync16(sb + SW_B + (uint32_t)(r * AST + g * 16), src);
    }
    CP_COMMIT();
    CP_WAIT0();
    __syncthreads();

    float acc[2][8][4];
    #pragma unroll
    for (int mf = 0; mf < 2; ++mf)
        #pragma unroll
        for (int nf = 0; nf < 8; ++nf)
            #pragma unroll
            for (int u = 0; u < 4; ++u) acc[mf][nf][u] = 0.f;

    uint32_t a_base = sb + SW_A + (lid & 15) * AST + ((lid >> 4) << 4);
    uint32_t b_base = sb + SW_B + (((lid >> 4) & 1) * 8 + (lid & 7)) * AST
                      + (((lid >> 3) & 1) << 4);

    #pragma unroll
    for (int step = 0; step < 6; ++step) {
        uint32_t kb = (uint32_t)(wid * 6 + step) * 32;
        uint32_t A0[4], A1[4];
        ldsm4(A0, a_base + kb);
        ldsm4(A1, a_base + 16 * AST + kb);
        #pragma unroll
        for (int nb = 0; nb < 4; ++nb) {
            uint32_t B[4];
            ldsm4(B, b_base + nb * 16 * AST + kb);
            hmma(acc[0][2 * nb],     A0, B[0], B[1]);
            hmma(acc[0][2 * nb + 1], A0, B[2], B[3]);
            hmma(acc[1][2 * nb],     A1, B[0], B[1]);
            hmma(acc[1][2 * nb + 1], A1, B[2], B[3]);
        }
    }
    __syncthreads();

    float* red = (float*)(sm + SW_RED);     // [8][2048]
    float* mine = red + wid * 2048;
    #pragma unroll
    for (int mf = 0; mf < 2; ++mf)
        #pragma unroll
        for (int nf = 0; nf < 8; ++nf)
            #pragma unroll
            for (int u = 0; u < 4; ++u) {
                int row = mf * 16 + (lid >> 2) + ((u >> 1) << 3);
                int col = nf * 8 + 2 * (lid & 3) + (u & 1);
                mine[row * 64 + col] = acc[mf][nf][u];
            }
    __syncthreads();

    #pragma unroll
    for (int it = 0; it < 8; ++it) {
        int idx = tid + it * 256;
        float v = 0.f;
        #pragma unroll
        for (int w = 0; w < 8; ++w) v += red[w * 2048 + idx];
        int row = idx >> 6, col = idx & 63;
        if (col < 32) g_Sw[((size_t)row * NB + col) * NS + s] = v;
        else          g_Srow[((size_t)row * NB + (col - 32)) * NS + s] = v;
    }
}

// ---------------------------------------------------------------------------
// Band v4: 512 threads, 16 warps x (16 rows x 48 cols). blk = j*32 + i.
// Warp w: rows [16w, 16w+16), exact window [clamp(16w-16,0,208), +48).
// Term set / order identical to R16 guarded layout -> bit-identical rel_err.
// ---------------------------------------------------------------------------
__device__ __forceinline__ void load_chunk(uint32_t sb, int buf, int c, int tid,
                                           const __half* Qp, const __half* Kp) {
    int k0 = c * KC;
    uint32_t bufb = sb + buf * BUF_SZ;
    #pragma unroll
    for (int it = 0; it < 2; ++it) {       // A: 1024 groups / 512 thr
        int x = tid + it * 512;
        int r = x >> 2, g = x & 3;
        size_t go = (size_t)r * NH + k0 + g * 8;
        cpasync16(bufb + O_A + (uint32_t)(r * ROWB + g * 16), Qp + go);
    }
    #pragma unroll
    for (int it = 0; it < 2; ++it) {       // B: 1024 groups / 512 thr
        int x = tid + it * 512;
        int r = x >> 2, g = x & 3;
        size_t go = (size_t)r * NH + k0 + g * 8;
        cpasync16(bufb + O_B + (uint32_t)(r * ROWB + g * 16), Kp + go);
    }
    CP_COMMIT();
}

__global__ void __launch_bounds__(512, 2)
li_band_kernel(const float* __restrict__ qmask, const float* __restrict__ kmask) {
    extern __shared__ char smem[];
    uint32_t sb = smem_u32(smem);

    int tid = threadIdx.x, wid = tid >> 5, lid = tid & 31;
    int blk = blockIdx.x;
    int j = blk >> 5;
    int i = blk & 31;

    float* ws = (float*)(smem + O_WS);
    float* km = (float*)(smem + O_KM);
    float* qm = (float*)(smem + O_QM);
    float* red = (float*)(smem + O_RED);
    if (tid < NS) {
        ws[tid] = g_w[tid];
        km[tid] = kmask[j * NS + tid];
        qm[tid] = qmask[i * NS + tid];
    }

    const __half* Qp = g_Qh + (size_t)i * NS * NH;
    const __half* Kp = g_Kh + (size_t)j * NS * NH;

    float acc[6][4];
    #pragma unroll
    for (int nf = 0; nf < 6; ++nf)
        #pragma unroll
        for (int u = 0; u < 4; ++u) acc[nf][u] = 0.f;

    int m_base = wid * 16;
    int wb = m_base - 16;
    if (wb < 0) wb = 0;
    if (wb > 208) wb = 208;

    uint32_t a_off = (uint32_t)((m_base + (lid & 15)) * ROWB + ((lid >> 4) << 4));
    uint32_t b_row = ((lid >> 4) & 1) * 8 + (lid & 7);
    uint32_t b_off = (uint32_t)((wb + b_row) * ROWB + ((lid >> 3) & 1) * 16);

    load_chunk(sb, 0, 0, tid, Qp, Kp);

    for (int c = 0; c < NCHUNK; ++c) {
        CP_WAIT0();
        __syncthreads();
        if (c + 1 < NCHUNK)
            load_chunk(sb, (c + 1) & 1, c + 1, tid, Qp, Kp);

        uint32_t base = sb + (c & 1) * BUF_SZ;
        #pragma unroll
        for (int ks = 0; ks < 2; ++ks) {
            uint32_t kb = ks * 32;
            uint32_t A[4], Bf[2][4];
            ldsm4(A, base + O_A + a_off + kb);
            ldsm4(Bf[0], base + O_B + b_off + kb);
            #pragma unroll
            for (int nb = 0; nb < 3; ++nb) {
                int cur = nb & 1;
                if (nb < 2)
                    ldsm4(Bf[cur ^ 1],
                          base + O_B + b_off + (nb + 1) * 16 * ROWB + kb);
                hmma(acc[2 * nb],     A, Bf[cur][0], Bf[cur][1]);
                hmma(acc[2 * nb + 1], A, Bf[cur][2], Bf[cur][3]);
            }
        }
    }
    __syncthreads();

    // ---- epilogue: near-band exact + linear far field ----
    float shift = ws[0];
    float E = expf(-shift);
    float Mjv = g_Mj[j];
    const float* SwP = g_Sw + ((size_t)i * NB + j) * NS;
    const float* SrP = g_Srow + ((size_t)i * NB + j) * NS;

    int cb = 2 * (lid & 3);
    int rloc = lid >> 2;
    float warp_score = 0.f;
    #pragma unroll
    for (int half = 0; half < 2; ++half) {
        int s = m_base + rloc + half * 8;
        float cse = 0.f, csec = 0.f;
        #pragma unroll
        for (int nf = 0; nf < 6; ++nf) {
            #pragma unroll
            for (int cc = 0; cc < 2; ++cc) {
                int t = wb + nf * 8 + cb + cc;
                if (km[t] > 0.f) {
                    float sim = acc[nf][half * 2 + cc];
                    int d = s - t; d = d < 0 ? -d : d;
                    float l = sim * ws[d];
                    float e = __expf(l - shift);
                    cse += e - E * (1.f + l);
                    csec = fmaf(e - E, sim, csec);
                }
            }
        }
        cse  += __shfl_xor_sync(0xffffffffu, cse, 1);
        cse  += __shfl_xor_sync(0xffffffffu, cse, 2);
        csec += __shfl_xor_sync(0xffffffffu, csec, 1);
        csec += __shfl_xor_sync(0xffffffffu, csec, 2);
        if ((lid & 3) == 0) {
            float qms = qm[s];
            float se = E * (Mjv + SwP[s]) + cse;
            float sec = E * SrP[s] + csec;
            if (se > 0.f && qms > 0.f) warp_score += (sec / se) * qms;
        }
    }
    #pragma unroll
    for (int o = 16; o; o >>= 1)
        warp_score += __shfl_xor_sync(0xffffffffu, warp_score, o);
    if (lid == 0) red[wid] = warp_score;
    __syncthreads();
    if (tid == 0) {
        float tot = 0.f;
        #pragma unroll
        for (int w = 0; w < 16; ++w) tot += red[w];
        g_partial[blk] = tot;
    }
}

// ---------------------------------------------------------------------------
__global__ void reduce_kernel(const float* __restrict__ qmask, float* __restrict__ out) {
    int i = blockIdx.x;
    int tid = threadIdx.x;
    float v = qmask[i * NS + tid];
    #pragma unroll
    for (int o = 16; o; o >>= 1) v += __shfl_xor_sync(0xffffffffu, v, o);
    __shared__ float red[8];
    __shared__ float qsum_s;
    if ((tid & 31) == 0) red[tid >> 5] = v;
    __syncthreads();
    if (tid == 0) {
        float t = 0.f;
        #pragma unroll
        for (int w = 0; w < 8; ++w) t += red[w];
        qsum_s = fmaxf(t, 1.f);
    }
    __syncthreads();
    if (tid < NB) {
        int jj = tid;
        out[i * NB + jj] = g_partial[jj * NB + i] / qsum_s;
    }
}

extern "C" void kernel_launch(void* const* d_in, const int* in_sizes, int n_in,
                              void* d_out, int out_size) {
    const float* q           = (const float*)d_in[0];
    const float* k           = (const float*)d_in[1];
    const float* qmask       = (const float*)d_in[2];
    const float* kmask       = (const float*)d_in[3];
    const float* alpha_raw   = (const float*)d_in[4];
    const float* logit_scale = (const float*)d_in[5];
    float* out = (float*)d_out;

    cudaFuncSetAttribute(li_band_kernel, cudaFuncAttributeMaxDynamicSharedMemorySize, SMEM_NEED);
    cudaFuncSetAttribute(swrow_kernel, cudaFuncAttributeMaxDynamicSharedMemorySize, SW_SMEM);
    cudaFuncSetAttribute(conv_kernel, cudaFuncAttributeMaxDynamicSharedMemorySize, CONV_SMEM);

    norm_all_kernel<<<2 * NB * NS / 8, 256>>>(q, k, alpha_raw, logit_scale);
    conv_kernel<<<NB * 3, 256, CONV_SMEM>>>(kmask, alpha_raw, logit_scale);
    swrow_kernel<<<NS, 256, SW_SMEM>>>();
    li_band_kernel<<<NB * NB, 512, SMEM_NEED>>>(qmask, kmask);
    reduce_kernel<<<NB, 256>>>(qmask, out);
}